// round 13
// baseline (speedup 1.0000x reference)
#include <cuda_runtime.h>

// TTN_Conv_2by2to1: out[n,p,o,x,y] = sum_{c,m} patch[n,c,m,x,y]*W[c,p,x,y,m,o] + bias
// patch m=(ij,kl): ab[ij]*cd[kl] from the 2x2 corners of x.
//
// One block per (x,y), 128 threads, thread = one n, all 48 (p,o) outputs.
// Main-loop smem reads are BROADCAST-ONLY: native-layout weight rows as
// m-pair LDS.128 (all lanes same address), plus one scalar ab load per ij.
// cd[16] is scalar in registers (kl fully unrolled). acc packs f32x2 over o.
// 56 KB smem -> 3 CTAs/SM, reg cap 170 (off the 128-reg wall at last).

#define NUM   128
#define CIN   3
#define COUT  8
#define NXY   961
#define DOUT  6
#define SX    32
#define SY    32
#define WPP   1536                    // floats per (c,p,xy) weight slice

#define W_FLOATS 12288                // 48 KB native weights [p][m*6+o]
#define AB_OFF   W_FLOATS             // ab table [ij][n], 16*128 floats
#define SMEM_BYTES ((W_FLOATS + 16*128)*4)   // 57344 B -> 3 CTAs/SM

typedef unsigned long long ull;

__device__ __forceinline__ ull pack2(float lo, float hi) {
    ull r; asm("mov.b64 %0, {%1,%2};" : "=l"(r) : "f"(lo), "f"(hi)); return r;
}
__device__ __forceinline__ void unpack2(ull v, float& lo, float& hi) {
    asm("mov.b64 {%0,%1}, %2;" : "=f"(lo), "=f"(hi) : "l"(v));
}
__device__ __forceinline__ void ffma2(ull& d, ull a, ull b) {
    asm("fma.rn.f32x2 %0, %1, %2, %0;" : "+l"(d) : "l"(a), "l"(b));
}

__global__ __launch_bounds__(128, 3)
void ttn_kernel(const float* __restrict__ x,
                const float* __restrict__ w,
                const float* __restrict__ bias,
                float* __restrict__ out)
{
    extern __shared__ float smem[];
    float* w_s  = smem;            // [p][m*6+o], native order
    float* ab_t = smem + AB_OFF;   // [ij][n]

    const int tid = threadIdx.x;   // = n (0..127)
    const int xy  = blockIdx.x;
    const int Xi  = xy / 31;
    const int Yi  = xy - Xi * 31;

    // acc[p][opair]: opair 0 -> (o0,o1), 1 -> (o2,o3), 2 -> (o4,o5)
    ull acc[COUT][3];
    #pragma unroll
    for (int p = 0; p < COUT; ++p)
        #pragma unroll
        for (int op = 0; op < 3; ++op) acc[p][op] = 0ULL;

    const int corner = Xi * SY + Yi;

    for (int c = 0; c < CIN; ++c) {
        // ---- stage weights: straight float4 copy, native layout ----
        {
            const float* wc = w + ((size_t)(c * COUT) * NXY + xy) * WPP;
            const size_t pstride = (size_t)NXY * WPP;
            #pragma unroll
            for (int it = 0; it < 24; ++it) {
                int idx = tid + it * 128;          // 3072 float4 total
                int pp  = idx / 384;               // 384 float4 per p
                int r   = idx - pp * 384;
                float4 v = __ldg(reinterpret_cast<const float4*>(wc + pp * pstride) + r);
                *reinterpret_cast<float4*>(w_s + pp * WPP + r * 4) = v;
            }
        }
        // ---- ab table to smem (tiny), cd to REGISTERS (this thread's n) ----
        float cd[16];
        {
            const float* xp = x + ((size_t)(tid * CIN + c) * 4) * (SX * SY) + corner;
            float av[4], bv[4], cv[4], dv[4];
            #pragma unroll
            for (int i = 0; i < 4; ++i) {
                av[i] = __ldg(xp + i * (SX * SY));            // (X  , Y  )
                bv[i] = __ldg(xp + i * (SX * SY) + SY);       // (X+1, Y  )
                cv[i] = __ldg(xp + i * (SX * SY) + 1);        // (X  , Y+1)
                dv[i] = __ldg(xp + i * (SX * SY) + SY + 1);   // (X+1, Y+1)
            }
            #pragma unroll
            for (int i = 0; i < 4; ++i)
                #pragma unroll
                for (int j = 0; j < 4; ++j) {
                    ab_t[(i * 4 + j) * NUM + tid] = av[i] * bv[j];
                    cd[i * 4 + j] = cv[i] * dv[j];
                }
        }
        __syncthreads();

        // ---- main loop: broadcast weight LDS.128, per-lane patch scalars ----
        for (int ij = 0; ij < 16; ++ij) {
            const float abv = ab_t[ij * NUM + tid];   // 1 wavefront (contig)
            #pragma unroll
            for (int klp = 0; klp < 8; ++klp) {
                const int m0 = (ij << 4) + (klp << 1);     // even m
                const float pm0 = abv * cd[2 * klp];
                const float pm1 = abv * cd[2 * klp + 1];
                const ull pd0 = pack2(pm0, pm0);
                const ull pd1 = pack2(pm1, pm1);
                #pragma unroll
                for (int p = 0; p < COUT; ++p) {
                    // broadcast LDS.128 x3: native rows of (m0, m0+1) for p
                    const ulonglong2* wr = reinterpret_cast<const ulonglong2*>(
                        w_s + p * WPP + m0 * 6);
                    ulonglong2 wA = wr[0];   // m0:(o0,o1)(o2,o3)
                    ulonglong2 wB = wr[1];   // m0:(o4,o5) m1:(o0,o1)
                    ulonglong2 wC = wr[2];   // m1:(o2,o3)(o4,o5)
                    ffma2(acc[p][0], pd0, wA.x);
                    ffma2(acc[p][1], pd0, wA.y);
                    ffma2(acc[p][2], pd0, wB.x);
                    ffma2(acc[p][0], pd1, wB.y);
                    ffma2(acc[p][1], pd1, wC.x);
                    ffma2(acc[p][2], pd1, wC.y);
                }
            }
        }
        __syncthreads();   // protect smem before next c's staging
    }

    // ---- epilogue: bias + store out[n][p][o][xy] ----
    const size_t nb = (size_t)tid * (COUT * DOUT * NXY) + xy;
    #pragma unroll
    for (int p = 0; p < COUT; ++p) {
        #pragma unroll
        for (int op = 0; op < 3; ++op) {
            float lo, hi;
            unpack2(acc[p][op], lo, hi);
            const int o = 2 * op;
            const float b0 = __ldg(bias + ((size_t)p * NXY + xy) * DOUT + o);
            const float b1 = __ldg(bias + ((size_t)p * NXY + xy) * DOUT + o + 1);
            out[nb + (size_t)(p * DOUT + o)     * NXY] = lo + b0;
            out[nb + (size_t)(p * DOUT + o + 1) * NXY] = hi + b1;
        }
    }
}

extern "C" void kernel_launch(void* const* d_in, const int* in_sizes, int n_in,
                              void* d_out, int out_size)
{
    const float* x    = (const float*)d_in[0];
    const float* w    = (const float*)d_in[1];
    const float* bias = (const float*)d_in[2];
    float* out = (float*)d_out;

    cudaFuncSetAttribute(ttn_kernel,
                         cudaFuncAttributeMaxDynamicSharedMemorySize, SMEM_BYTES);
    ttn_kernel<<<NXY, 128, SMEM_BYTES>>>(x, w, bias, out);
}